// round 1
// baseline (speedup 1.0000x reference)
#include <cuda_runtime.h>
#include <cstdint>

// Problem dims (fixed by the dataset)
#define N_  64
#define C_  256
#define T_  64
#define V_  50
#define H_  16
#define P_  10
#define TV  (T_ * V_)          // 3200
#define RED_THREADS 400        // multiple of V_ => fixed v per thread
#define RED_ITERS   8          // 400*8 = 3200

// output column j -> input column v (concat order of PARTS)
__constant__ int c_cmap[V_] = {
    0,1,2,3,20,            // p0
    8,9,10,11,23,24,       // p1
    16,17,18,19,           // p2
    4,5,6,7,21,22,         // p3
    12,13,14,15,           // p4
    25,26,27,28,45,        // p5
    33,34,35,36,48,49,     // p6
    41,42,43,44,           // p7
    29,30,31,32,46,47,     // p8
    37,38,39,40            // p9
};
// output column j -> partition
__constant__ int c_pmap[V_] = {
    0,0,0,0,0,
    1,1,1,1,1,1,
    2,2,2,2,
    3,3,3,3,3,3,
    4,4,4,4,
    5,5,5,5,5,
    6,6,6,6,6,6,
    7,7,7,7,
    8,8,8,8,8,8,
    9,9,9,9
};
// partition -> member input columns (padded to 6) and sizes
__constant__ int c_pvs[P_ * 6] = {
    0,1,2,3,20,0,
    8,9,10,11,23,24,
    16,17,18,19,0,0,
    4,5,6,7,21,22,
    12,13,14,15,0,0,
    25,26,27,28,45,0,
    33,34,35,36,48,49,
    41,42,43,44,0,0,
    29,30,31,32,46,47,
    37,38,39,40,0,0
};
__constant__ int c_psize[P_] = {5,6,4,6,4,5,6,4,6,4};

// Scratch (alloc-free rule: __device__ globals). Layout: [n][p][c]
__device__ float g_avg [N_ * P_ * C_];
__device__ float g_max [N_ * P_ * C_];
__device__ float g_gate[N_ * P_ * C_];

// ---------------------------------------------------------------------------
// Kernel 1: per-(n,c) sum+max over (t, v in part) for all 10 parts.
// One block per (n,c) slab of 3200 contiguous floats. Threads have fixed v.
// ---------------------------------------------------------------------------
__global__ __launch_bounds__(RED_THREADS)
void reduce_kernel(const float* __restrict__ x)
{
    const int nc  = blockIdx.x;             // n*C_ + c
    const int tid = threadIdx.x;            // 0..399
    const float* xb = x + (size_t)nc * TV;

    float s = 0.f;
    float m = -3.402823466e+38f;
#pragma unroll
    for (int k = 0; k < RED_ITERS; ++k) {
        float val = xb[tid + RED_THREADS * k];   // fully coalesced
        s += val;
        m = fmaxf(m, val);
    }

    __shared__ float ss[RED_THREADS];
    __shared__ float sm[RED_THREADS];
    ss[tid] = s;
    sm[tid] = m;
    __syncthreads();

    // stage 2: reduce the 8 t-groups per column v  (tid < 50)
    if (tid < V_) {
        float s2 = 0.f, m2 = -3.402823466e+38f;
#pragma unroll
        for (int g = 0; g < RED_ITERS; ++g) {
            s2 += ss[tid + V_ * g];
            m2 = fmaxf(m2, sm[tid + V_ * g]);
        }
        ss[tid] = s2;   // same-thread read->write, safe
        sm[tid] = m2;
    }
    __syncthreads();

    // stage 3: combine columns belonging to each part  (tid < 10)
    if (tid < P_) {
        const int sz = c_psize[tid];
        float s3 = 0.f, m3 = -3.402823466e+38f;
        for (int j = 0; j < sz; ++j) {
            int vv = c_pvs[tid * 6 + j];
            s3 += ss[vv];
            m3 = fmaxf(m3, sm[vv]);
        }
        const int n = nc >> 8;      // C_ = 256
        const int c = nc & 255;
        const size_t o = ((size_t)n * P_ + tid) * C_ + c;
        g_avg[o] = s3 / (float)(T_ * sz);
        g_max[o] = m3;
    }
}

// ---------------------------------------------------------------------------
// Kernel 2: gate[n,p,c] = sigmoid( W2 @ (relu(W1@avg+b1)+relu(W1@mx+b1)) + 2*b2 )
// One block per (n,p), 256 threads.
// ---------------------------------------------------------------------------
__global__ __launch_bounds__(C_)
void gate_kernel(const float* __restrict__ W1, const float* __restrict__ b1,
                 const float* __restrict__ W2, const float* __restrict__ b2)
{
    const int np = blockIdx.x;
    const int n  = np / P_;
    const int p  = np % P_;
    const int tid = threadIdx.x;

    __shared__ float sa[C_];
    __shared__ float sx[C_];
    __shared__ float hs[H_];

    const size_t base = ((size_t)n * P_ + p) * C_;
    sa[tid] = g_avg[base + tid];
    sx[tid] = g_max[base + tid];
    __syncthreads();

    const int w = tid >> 5;     // warp 0..7
    const int l = tid & 31;

    // warp w computes h rows i = w and i = w+8
#pragma unroll
    for (int ii = 0; ii < 2; ++ii) {
        const int i = w + 8 * ii;
        const float* w1 = W1 + ((size_t)p * H_ + i) * C_;
        float da = 0.f, dm = 0.f;
#pragma unroll
        for (int k = 0; k < 8; ++k) {
            const int c = l + 32 * k;
            const float wv = w1[c];
            da += wv * sa[c];
            dm += wv * sx[c];
        }
#pragma unroll
        for (int off = 16; off > 0; off >>= 1) {
            da += __shfl_down_sync(0xffffffffu, da, off);
            dm += __shfl_down_sync(0xffffffffu, dm, off);
        }
        if (l == 0) {
            const float bb = b1[p * H_ + i];
            hs[i] = fmaxf(da + bb, 0.f) + fmaxf(dm + bb, 0.f);
        }
    }
    __syncthreads();

    const float* w2 = W2 + ((size_t)p * C_ + tid) * H_;
    float acc = 2.f * b2[p * C_ + tid];
#pragma unroll
    for (int k = 0; k < H_; ++k)
        acc += w2[k] * hs[k];

    g_gate[base + tid] = 1.f / (1.f + __expf(-acc));
}

// ---------------------------------------------------------------------------
// Kernel 3: out[n,c,t,j] = x[n,c,t,cmap[j]] * gate[n, pmap[j], c]
// One block per (n,c) slab; contiguous writes, within-row permuted reads.
// ---------------------------------------------------------------------------
__global__ __launch_bounds__(RED_THREADS)
void scale_kernel(const float* __restrict__ x, float* __restrict__ out)
{
    const int nc  = blockIdx.x;
    const int tid = threadIdx.x;
    const int n = nc >> 8;
    const int c = nc & 255;

    const int j  = tid % V_;          // fixed output column per thread
    const int p  = c_pmap[j];
    const int cm = c_cmap[j];

    const float g = g_gate[((size_t)n * P_ + p) * C_ + c];

    const float* xb = x   + (size_t)nc * TV;
    float*       ob = out + (size_t)nc * TV;

    const int rbase = tid - j + cm;   // same t-row, permuted column
#pragma unroll
    for (int k = 0; k < RED_ITERS; ++k)
        ob[tid + RED_THREADS * k] = xb[rbase + RED_THREADS * k] * g;
}

// ---------------------------------------------------------------------------
extern "C" void kernel_launch(void* const* d_in, const int* in_sizes, int n_in,
                              void* d_out, int out_size)
{
    const float* x  = (const float*)d_in[0];
    const float* W1 = (const float*)d_in[1];
    const float* b1 = (const float*)d_in[2];
    const float* W2 = (const float*)d_in[3];
    const float* b2 = (const float*)d_in[4];
    float* out = (float*)d_out;

    reduce_kernel<<<N_ * C_, RED_THREADS>>>(x);
    gate_kernel<<<N_ * P_, C_>>>(W1, b1, W2, b2);
    scale_kernel<<<N_ * C_, RED_THREADS>>>(x, out);
}

// round 2
// speedup vs baseline: 1.2759x; 1.2759x over previous
#include <cuda_runtime.h>
#include <cstdint>

// Problem dims (fixed by the dataset)
#define N_  64
#define C_  256
#define T_  64
#define V_  50
#define H_  16
#define P_  10
#define TV  (T_ * V_)          // 3200 floats = 800 float4 per (n,c) slab

// output column j -> input column v (concat order of PARTS)
__constant__ int c_cmap[V_] = {
    0,1,2,3,20,
    8,9,10,11,23,24,
    16,17,18,19,
    4,5,6,7,21,22,
    12,13,14,15,
    25,26,27,28,45,
    33,34,35,36,48,49,
    41,42,43,44,
    29,30,31,32,46,47,
    37,38,39,40
};
// output column j -> partition
__constant__ int c_pmap[V_] = {
    0,0,0,0,0,
    1,1,1,1,1,1,
    2,2,2,2,
    3,3,3,3,3,3,
    4,4,4,4,
    5,5,5,5,5,
    6,6,6,6,6,6,
    7,7,7,7,
    8,8,8,8,8,8,
    9,9,9,9
};
// partition -> member input columns (padded to 6) and sizes
__constant__ int c_pvs[P_ * 6] = {
    0,1,2,3,20,0,
    8,9,10,11,23,24,
    16,17,18,19,0,0,
    4,5,6,7,21,22,
    12,13,14,15,0,0,
    25,26,27,28,45,0,
    33,34,35,36,48,49,
    41,42,43,44,0,0,
    29,30,31,32,46,47,
    37,38,39,40,0,0
};
__constant__ int c_psize[P_] = {5,6,4,6,4,5,6,4,6,4};

// Scratch (alloc-free rule: __device__ globals). Layout: [n][p][c]
__device__ float g_avg [N_ * P_ * C_];
__device__ float g_max [N_ * P_ * C_];
__device__ float g_gate[N_ * P_ * C_];

// ---------------------------------------------------------------------------
// Kernel 1: per-(n,c) sum+max over (t, v in part) for all 10 parts.
// 256 threads/block, one 3200-float slab per block. float4 loads -> shared,
// then per-column reduce (conflict-free), then part combine.
// ---------------------------------------------------------------------------
__global__ __launch_bounds__(256)
void reduce_kernel(const float4* __restrict__ x4)
{
    __shared__ float4 sh4[TV / 4];          // 12.8 KB
    __shared__ float  cs[V_ + 2];
    __shared__ float  cmx[V_ + 2];
    float* sh = (float*)sh4;

    const int nc  = blockIdx.x;             // n*C_ + c
    const int tid = threadIdx.x;
    const float4* xb = x4 + (size_t)nc * (TV / 4);

    // Phase A: coalesced 128-bit loads into shared (800 = 3*256 + 32)
#pragma unroll
    for (int k = 0; k < 3; ++k)
        sh4[tid + 256 * k] = xb[tid + 256 * k];
    if (tid < 32)
        sh4[tid + 768] = xb[tid + 768];
    __syncthreads();

    // Phase B: 50 threads, each reduces its column over 64 rows
    if (tid < V_) {
        float s = 0.f, m = -3.402823466e+38f;
#pragma unroll
        for (int r = 0; r < T_; ++r) {
            float v = sh[r * V_ + tid];
            s += v;
            m = fmaxf(m, v);
        }
        cs[tid]  = s;
        cmx[tid] = m;
    }
    __syncthreads();

    // Phase C: 10 threads combine part columns
    if (tid < P_) {
        const int sz = c_psize[tid];
        float s3 = 0.f, m3 = -3.402823466e+38f;
        for (int j = 0; j < sz; ++j) {
            const int vv = c_pvs[tid * 6 + j];
            s3 += cs[vv];
            m3 = fmaxf(m3, cmx[vv]);
        }
        const int n = nc >> 8;      // C_ = 256
        const int c = nc & 255;
        const size_t o = ((size_t)n * P_ + tid) * C_ + c;
        g_avg[o] = s3 / (float)(T_ * sz);
        g_max[o] = m3;
    }
}

// ---------------------------------------------------------------------------
// Kernel 2: gate[n,p,c] = sigmoid( W2 @ (relu(W1@avg+b1)+relu(W1@mx+b1)) + 2*b2 )
// One block per (n,p), 256 threads.
// ---------------------------------------------------------------------------
__global__ __launch_bounds__(C_)
void gate_kernel(const float* __restrict__ W1, const float* __restrict__ b1,
                 const float* __restrict__ W2, const float* __restrict__ b2)
{
    const int np = blockIdx.x;
    const int n  = np / P_;
    const int p  = np % P_;
    const int tid = threadIdx.x;

    __shared__ float sa[C_];
    __shared__ float sx[C_];
    __shared__ float hs[H_];

    const size_t base = ((size_t)n * P_ + p) * C_;
    sa[tid] = g_avg[base + tid];
    sx[tid] = g_max[base + tid];
    __syncthreads();

    const int w = tid >> 5;     // warp 0..7
    const int l = tid & 31;

    // warp w computes h rows i = w and i = w+8
#pragma unroll
    for (int ii = 0; ii < 2; ++ii) {
        const int i = w + 8 * ii;
        const float* w1 = W1 + ((size_t)p * H_ + i) * C_;
        float da = 0.f, dm = 0.f;
#pragma unroll
        for (int k = 0; k < 8; ++k) {
            const int c = l + 32 * k;
            const float wv = w1[c];
            da += wv * sa[c];
            dm += wv * sx[c];
        }
#pragma unroll
        for (int off = 16; off > 0; off >>= 1) {
            da += __shfl_down_sync(0xffffffffu, da, off);
            dm += __shfl_down_sync(0xffffffffu, dm, off);
        }
        if (l == 0) {
            const float bb = b1[p * H_ + i];
            hs[i] = fmaxf(da + bb, 0.f) + fmaxf(dm + bb, 0.f);
        }
    }
    __syncthreads();

    const float* w2 = W2 + ((size_t)p * C_ + tid) * H_;
    float acc = 2.f * b2[p * C_ + tid];
#pragma unroll
    for (int k = 0; k < H_; ++k)
        acc += w2[k] * hs[k];

    g_gate[base + tid] = 1.f / (1.f + __expf(-acc));
}

// ---------------------------------------------------------------------------
// Kernel 3: out[n,c,t,j] = x[n,c,t,cmap[j]] * gate[n, pmap[j], c]
// float4 staged through shared; permutation + per-column gate from shared.
// ---------------------------------------------------------------------------
__global__ __launch_bounds__(256)
void scale_kernel(const float4* __restrict__ x4, float4* __restrict__ out4)
{
    __shared__ float4 sh4[TV / 4];          // 12.8 KB
    __shared__ float  gcol[V_ + 2];         // gate per OUTPUT column
    __shared__ int    scm[V_ + 2];          // output col -> input col
    float* sh = (float*)sh4;

    const int nc  = blockIdx.x;
    const int tid = threadIdx.x;
    const int n = nc >> 8;
    const int c = nc & 255;

    const float4* xb = x4   + (size_t)nc * (TV / 4);
    float4*       ob = out4 + (size_t)nc * (TV / 4);

    // Phase A: coalesced loads into shared; small threads also stage maps
#pragma unroll
    for (int k = 0; k < 3; ++k)
        sh4[tid + 256 * k] = xb[tid + 256 * k];
    if (tid < 32)
        sh4[tid + 768] = xb[tid + 768];
    if (tid < V_) {
        scm[tid]  = c_cmap[tid];
        gcol[tid] = g_gate[((size_t)n * P_ + c_pmap[tid]) * C_ + c];
    }
    __syncthreads();

    // Phase B: 128-bit stores; 4 permuted gathers from shared each
#pragma unroll
    for (int k = 0; k < 4; ++k) {
        const int i = tid + 256 * k;        // float4 index 0..799
        if (k < 3 || i < TV / 4) {
            const int j0 = 4 * i;
            float4 o;
#pragma unroll
            for (int e = 0; e < 4; ++e) {
                const int jj  = j0 + e;
                const int row = jj / V_;
                const int col = jj - row * V_;
                ((float*)&o)[e] = sh[row * V_ + scm[col]] * gcol[col];
            }
            ob[i] = o;
        }
    }
}

// ---------------------------------------------------------------------------
extern "C" void kernel_launch(void* const* d_in, const int* in_sizes, int n_in,
                              void* d_out, int out_size)
{
    const float* x  = (const float*)d_in[0];
    const float* W1 = (const float*)d_in[1];
    const float* b1 = (const float*)d_in[2];
    const float* W2 = (const float*)d_in[3];
    const float* b2 = (const float*)d_in[4];

    reduce_kernel<<<N_ * C_, 256>>>((const float4*)x);
    gate_kernel<<<N_ * P_, C_>>>(W1, b1, W2, b2);
    scale_kernel<<<N_ * C_, 256>>>((const float4*)x, (float4*)d_out);
}

// round 3
// speedup vs baseline: 1.3399x; 1.0502x over previous
#include <cuda_runtime.h>
#include <cstdint>

// Problem dims (fixed by the dataset)
#define N_  64
#define C_  256
#define T_  64
#define V_  50
#define H_  16
#define P_  10
#define TV  (T_ * V_)          // 3200 floats = 800 float4 per (n,c) slab

// output column j -> input column v (concat order of PARTS)
__constant__ int c_cmap[V_] = {
    0,1,2,3,20,
    8,9,10,11,23,24,
    16,17,18,19,
    4,5,6,7,21,22,
    12,13,14,15,
    25,26,27,28,45,
    33,34,35,36,48,49,
    41,42,43,44,
    29,30,31,32,46,47,
    37,38,39,40
};
// output column j -> partition
__constant__ int c_pmap[V_] = {
    0,0,0,0,0,
    1,1,1,1,1,1,
    2,2,2,2,
    3,3,3,3,3,3,
    4,4,4,4,
    5,5,5,5,5,
    6,6,6,6,6,6,
    7,7,7,7,
    8,8,8,8,8,8,
    9,9,9,9
};
// partition -> member input columns (padded to 6) and sizes
__constant__ int c_pvs[P_ * 6] = {
    0,1,2,3,20,0,
    8,9,10,11,23,24,
    16,17,18,19,0,0,
    4,5,6,7,21,22,
    12,13,14,15,0,0,
    25,26,27,28,45,0,
    33,34,35,36,48,49,
    41,42,43,44,0,0,
    29,30,31,32,46,47,
    37,38,39,40,0,0
};
__constant__ int c_psize[P_] = {5,6,4,6,4,5,6,4,6,4};

// Scratch (alloc-free rule: __device__ globals). Layout: [n][p][c]
__device__ float g_avg [N_ * P_ * C_];
__device__ float g_max [N_ * P_ * C_];
__device__ float g_gate[N_ * P_ * C_];

// ---------------------------------------------------------------------------
// Kernel 1: per-(n,c) sum+max over (t, v in part) for all 10 parts.
// 256 thr/block. float4 loads -> shared; phase B over 200 threads
// (50 cols x 4 row-groups of 16 rows), then 50-thread combine, then parts.
// ---------------------------------------------------------------------------
__global__ __launch_bounds__(256)
void reduce_kernel(const float4* __restrict__ x4)
{
    __shared__ float4 sh4[TV / 4];          // 12.8 KB
    __shared__ float  ps[200];
    __shared__ float  pm[200];
    __shared__ float  cs[V_ + 2];
    __shared__ float  cmx[V_ + 2];
    float* sh = (float*)sh4;

    const int nc  = blockIdx.x;             // n*C_ + c
    const int tid = threadIdx.x;
    const float4* xb = x4 + (size_t)nc * (TV / 4);

    // Phase A: coalesced 128-bit loads into shared (800 = 3*256 + 32)
#pragma unroll
    for (int k = 0; k < 3; ++k)
        sh4[tid + 256 * k] = xb[tid + 256 * k];
    if (tid < 32)
        sh4[tid + 768] = xb[tid + 768];
    __syncthreads();

    // Phase B: 200 threads, each reduces its column over 16 rows
    if (tid < 200) {
        const int col = tid % V_;
        const int r0  = (tid / V_) * 16;
        float s = 0.f, m = -3.402823466e+38f;
#pragma unroll
        for (int rr = 0; rr < 16; ++rr) {
            float v = sh[(r0 + rr) * V_ + col];
            s += v;
            m = fmaxf(m, v);
        }
        ps[tid] = s;
        pm[tid] = m;
    }
    __syncthreads();

    // Phase B2: 50 threads combine the 4 row-groups
    if (tid < V_) {
        float s = ps[tid] + ps[tid + 50] + ps[tid + 100] + ps[tid + 150];
        float m = fmaxf(fmaxf(pm[tid], pm[tid + 50]),
                        fmaxf(pm[tid + 100], pm[tid + 150]));
        cs[tid]  = s;
        cmx[tid] = m;
    }
    __syncthreads();

    // Phase C: 10 threads combine part columns
    if (tid < P_) {
        const int sz = c_psize[tid];
        float s3 = 0.f, m3 = -3.402823466e+38f;
        for (int j = 0; j < sz; ++j) {
            const int vv = c_pvs[tid * 6 + j];
            s3 += cs[vv];
            m3 = fmaxf(m3, cmx[vv]);
        }
        const int n = nc >> 8;      // C_ = 256
        const int c = nc & 255;
        const size_t o = ((size_t)n * P_ + tid) * C_ + c;
        g_avg[o] = s3 / (float)(T_ * sz);
        g_max[o] = m3;
    }
}

// ---------------------------------------------------------------------------
// Kernel 2: gate[n,p,c] = sigmoid( W2 @ (relu(W1@avg+b1)+relu(W1@mx+b1)) + 2*b2 )
// One block per (n,p), 256 threads.
// ---------------------------------------------------------------------------
__global__ __launch_bounds__(C_)
void gate_kernel(const float* __restrict__ W1, const float* __restrict__ b1,
                 const float* __restrict__ W2, const float* __restrict__ b2)
{
    const int np = blockIdx.x;
    const int n  = np / P_;
    const int p  = np % P_;
    const int tid = threadIdx.x;

    __shared__ float sa[C_];
    __shared__ float sx[C_];
    __shared__ float hs[H_];

    const size_t base = ((size_t)n * P_ + p) * C_;
    sa[tid] = g_avg[base + tid];
    sx[tid] = g_max[base + tid];
    __syncthreads();

    const int w = tid >> 5;     // warp 0..7
    const int l = tid & 31;

#pragma unroll
    for (int ii = 0; ii < 2; ++ii) {
        const int i = w + 8 * ii;
        const float* w1 = W1 + ((size_t)p * H_ + i) * C_;
        float da = 0.f, dm = 0.f;
#pragma unroll
        for (int k = 0; k < 8; ++k) {
            const int c = l + 32 * k;
            const float wv = w1[c];
            da += wv * sa[c];
            dm += wv * sx[c];
        }
#pragma unroll
        for (int off = 16; off > 0; off >>= 1) {
            da += __shfl_down_sync(0xffffffffu, da, off);
            dm += __shfl_down_sync(0xffffffffu, dm, off);
        }
        if (l == 0) {
            const float bb = b1[p * H_ + i];
            hs[i] = fmaxf(da + bb, 0.f) + fmaxf(dm + bb, 0.f);
        }
    }
    __syncthreads();

    const float* w2 = W2 + ((size_t)p * C_ + tid) * H_;
    float acc = 2.f * b2[p * C_ + tid];
#pragma unroll
    for (int k = 0; k < H_; ++k)
        acc += w2[k] * hs[k];

    g_gate[base + tid] = 1.f / (1.f + __expf(-acc));
}

// ---------------------------------------------------------------------------
// Kernel 3: out[n,c,t,j] = x[n,c,t,cmap[j]] * gate[n, pmap[j], c]
// float4 staged through shared (conflict-free STS.128). Gather phase is
// lane-stride-1 (conflict-free scalar LDS), no division (incremental col),
// one LDS.64 per element for the packed (gate, delta) table. Coalesced STG.32.
// ---------------------------------------------------------------------------
__global__ __launch_bounds__(256)
void scale_kernel(const float4* __restrict__ x4, float* __restrict__ out)
{
    __shared__ float4 sh4[TV / 4];          // 12.8 KB
    __shared__ float2 tab[V_ + 2];          // {gate, int_as_float(cmap[j]-j)}
    float* sh = (float*)sh4;

    const int nc  = blockIdx.x;
    const int tid = threadIdx.x;
    const int n = nc >> 8;
    const int c = nc & 255;

    const float4* xb = x4 + (size_t)nc * (TV / 4);
    float*        ob = out + (size_t)nc * TV;

    // Phase A: coalesced loads into shared; threads <50 stage per-col table
#pragma unroll
    for (int k = 0; k < 3; ++k)
        sh4[tid + 256 * k] = xb[tid + 256 * k];
    if (tid < 32)
        sh4[tid + 768] = xb[tid + 768];
    if (tid < V_) {
        const int j = tid;
        float2 t;
        t.x = g_gate[((size_t)n * P_ + c_pmap[j]) * C_ + c];
        t.y = __int_as_float(c_cmap[j] - j);
        tab[j] = t;
    }
    __syncthreads();

    // Phase B: lane-consecutive elements jj = tid + 256*m  (3200 = 12*256+128)
    int col = tid % V_;                 // output column of element tid
#pragma unroll
    for (int m = 0; m < 13; ++m) {
        if (m < 12 || tid < 128) {
            const int jj = tid + 256 * m;
            const float2 t = tab[col];
            const int d = __float_as_int(t.y);
            ob[jj] = sh[jj + d] * t.x;
        }
        // advance column by 256 mod 50 = 6
        col += 6;
        if (col >= V_) col -= V_;
    }
}

// ---------------------------------------------------------------------------
extern "C" void kernel_launch(void* const* d_in, const int* in_sizes, int n_in,
                              void* d_out, int out_size)
{
    const float* x  = (const float*)d_in[0];
    const float* W1 = (const float*)d_in[1];
    const float* b1 = (const float*)d_in[2];
    const float* W2 = (const float*)d_in[3];
    const float* b2 = (const float*)d_in[4];

    reduce_kernel<<<N_ * C_, 256>>>((const float4*)x);
    gate_kernel<<<N_ * P_, C_>>>(W1, b1, W2, b2);
    scale_kernel<<<N_ * C_, 256>>>((const float4*)x, (float*)d_out);
}